// round 11
// baseline (speedup 1.0000x reference)
#include <cuda_runtime.h>

// Elementwise clamp: out = min(max(x, -0.5f), 0.5f)
// N = 67108864 floats = 16777216 float4s. Each thread handles 4 float4s
// (front-batched loads for MLP=4). Block of 256 threads covers 1024 float4s.

#define VPT 4  // float4s per thread

__global__ void clip_kernel_v4x4(const float4* __restrict__ in,
                                 float4* __restrict__ out,
                                 int n4) {
    int base = blockIdx.x * (blockDim.x * VPT) + threadIdx.x;

    float4 v[VPT];
    // Front-batched loads: 4 independent LDG.128 in flight before any use.
    #pragma unroll
    for (int k = 0; k < VPT; k++) {
        int i = base + k * blockDim.x;
        if (i < n4) v[k] = __ldcs(&in[i]);
    }
    #pragma unroll
    for (int k = 0; k < VPT; k++) {
        v[k].x = fminf(fmaxf(v[k].x, -0.5f), 0.5f);
        v[k].y = fminf(fmaxf(v[k].y, -0.5f), 0.5f);
        v[k].z = fminf(fmaxf(v[k].z, -0.5f), 0.5f);
        v[k].w = fminf(fmaxf(v[k].w, -0.5f), 0.5f);
    }
    #pragma unroll
    for (int k = 0; k < VPT; k++) {
        int i = base + k * blockDim.x;
        if (i < n4) __stcs(&out[i], v[k]);
    }
}

// Scalar tail fallback for non-multiple-of-4 element counts (unused here).
__global__ void clip_kernel_tail(const float* __restrict__ in,
                                 float* __restrict__ out,
                                 int start, int n) {
    int i = start + blockIdx.x * blockDim.x + threadIdx.x;
    if (i < n) {
        out[i] = fminf(fmaxf(in[i], -0.5f), 0.5f);
    }
}

extern "C" void kernel_launch(void* const* d_in, const int* in_sizes, int n_in,
                              void* d_out, int out_size) {
    const float* x = (const float*)d_in[0];
    float* out = (float*)d_out;
    int n = in_sizes[0];

    int n4 = n >> 2;
    int tail_start = n4 << 2;

    if (n4 > 0) {
        const int threads = 256;
        const int elems_per_block = threads * VPT;  // 1024 float4s
        int blocks = (n4 + elems_per_block - 1) / elems_per_block;
        clip_kernel_v4x4<<<blocks, threads>>>((const float4*)x, (float4*)out, n4);
    }
    if (tail_start < n) {
        int rem = n - tail_start;
        const int threads = 256;
        int blocks = (rem + threads - 1) / threads;
        clip_kernel_tail<<<blocks, threads>>>(x, out, tail_start, n);
    }
}

// round 12
// speedup vs baseline: 1.0071x; 1.0071x over previous
#include <cuda_runtime.h>

// Elementwise clamp: out = min(max(x, -0.5f), 0.5f)
// N = 67108864 floats = 16777216 float4s. Each thread handles 4 float4s
// (front-batched loads for MLP=4). Block of 256 threads covers 1024 float4s.

#define VPT 4  // float4s per thread

__global__ void clip_kernel_v4x4(const float4* __restrict__ in,
                                 float4* __restrict__ out,
                                 int n4) {
    int base = blockIdx.x * (blockDim.x * VPT) + threadIdx.x;

    float4 v[VPT];
    // Front-batched loads: 4 independent LDG.128 in flight before any use.
    #pragma unroll
    for (int k = 0; k < VPT; k++) {
        int i = base + k * blockDim.x;
        if (i < n4) v[k] = __ldcs(&in[i]);
    }
    #pragma unroll
    for (int k = 0; k < VPT; k++) {
        v[k].x = fminf(fmaxf(v[k].x, -0.5f), 0.5f);
        v[k].y = fminf(fmaxf(v[k].y, -0.5f), 0.5f);
        v[k].z = fminf(fmaxf(v[k].z, -0.5f), 0.5f);
        v[k].w = fminf(fmaxf(v[k].w, -0.5f), 0.5f);
    }
    #pragma unroll
    for (int k = 0; k < VPT; k++) {
        int i = base + k * blockDim.x;
        if (i < n4) __stcs(&out[i], v[k]);
    }
}

// Scalar tail fallback for non-multiple-of-4 element counts (unused here).
__global__ void clip_kernel_tail(const float* __restrict__ in,
                                 float* __restrict__ out,
                                 int start, int n) {
    int i = start + blockIdx.x * blockDim.x + threadIdx.x;
    if (i < n) {
        out[i] = fminf(fmaxf(in[i], -0.5f), 0.5f);
    }
}

extern "C" void kernel_launch(void* const* d_in, const int* in_sizes, int n_in,
                              void* d_out, int out_size) {
    const float* x = (const float*)d_in[0];
    float* out = (float*)d_out;
    int n = in_sizes[0];

    int n4 = n >> 2;
    int tail_start = n4 << 2;

    if (n4 > 0) {
        const int threads = 256;
        const int elems_per_block = threads * VPT;  // 1024 float4s
        int blocks = (n4 + elems_per_block - 1) / elems_per_block;
        clip_kernel_v4x4<<<blocks, threads>>>((const float4*)x, (float4*)out, n4);
    }
    if (tail_start < n) {
        int rem = n - tail_start;
        const int threads = 256;
        int blocks = (rem + threads - 1) / threads;
        clip_kernel_tail<<<blocks, threads>>>(x, out, tail_start, n);
    }
}